// round 1
// baseline (speedup 1.0000x reference)
#include <cuda_runtime.h>
#include <cstdint>

#define NN 50000
#define EE 800000
#define HIDF 128
#define NCLS 40
#define LNEPS 1e-5f

// ---------------- scratch (device globals; no allocation allowed) ----------------
__device__ float g_h[(size_t)NN * HIDF];     // post-GEMM features
__device__ float g_act[(size_t)NN * HIDF];   // post-LN activations
__device__ float g_dinv[NN];
__device__ int   g_deg[NN];
__device__ int   g_row[NN + 1];
__device__ int   g_cursor[NN];
__device__ int   g_srcE[EE];
__device__ int   g_dstE[EE];
__device__ int   g_csrc[EE];                 // CSR src lists grouped by dst
__device__ int   g_is64;

// ---------------- f32x2 packed math helpers (sm_103a) ----------------
__device__ __forceinline__ unsigned long long dup2(float a) {
    unsigned long long r;
    unsigned u = __float_as_uint(a);
    asm("mov.b64 %0, {%1, %1};" : "=l"(r) : "r"(u));
    return r;
}
__device__ __forceinline__ void fma2(unsigned long long& d, unsigned long long a,
                                     unsigned long long b) {
    asm("fma.rn.f32x2 %0, %1, %2, %0;" : "+l"(d) : "l"(a), "l"(b));
}

// ---------------- edge index dtype detection + conversion ----------------
__global__ void detect_kernel(const void* ei) {
    const long long* p = (const long long*)ei;
    int ok = 1;
    for (int i = 0; i < 128; i++) {
        long long v = p[i];
        if (v < 0 || v >= NN) { ok = 0; break; }
    }
    g_is64 = ok;
}

__global__ void convert_edges(const void* __restrict__ ei, int E) {
    int e = blockIdx.x * blockDim.x + threadIdx.x;
    if (e >= E) return;
    if (g_is64) {
        const long long* p = (const long long*)ei;
        g_srcE[e] = (int)p[e];
        g_dstE[e] = (int)p[E + e];
    } else {
        const int* p = (const int*)ei;
        g_srcE[e] = p[e];
        g_dstE[e] = p[E + e];
    }
}

// ---------------- CSR build ----------------
__global__ void zero_deg(int N) {
    int i = blockIdx.x * blockDim.x + threadIdx.x;
    if (i < N) g_deg[i] = 0;
}
__global__ void count_kernel(int E) {
    int e = blockIdx.x * blockDim.x + threadIdx.x;
    if (e < E) atomicAdd(&g_deg[g_dstE[e]], 1);
}
__global__ void scan_kernel(int N) {
    __shared__ int part[1024];
    int tid = threadIdx.x;
    int chunk = (N + 1023) / 1024;
    int b = tid * chunk;
    int e = min(b + chunk, N);
    int s = 0;
    for (int i = b; i < e; i++) s += g_deg[i];
    part[tid] = s;
    __syncthreads();
    for (int off = 1; off < 1024; off <<= 1) {
        int v = (tid >= off) ? part[tid - off] : 0;
        __syncthreads();
        part[tid] += v;
        __syncthreads();
    }
    int run = (tid == 0) ? 0 : part[tid - 1];
    for (int i = b; i < e; i++) {
        g_row[i] = run;
        g_cursor[i] = run;
        run += g_deg[i];
    }
    if (tid == 1023) g_row[N] = run;
}
__global__ void dinv_kernel(int N) {
    int i = blockIdx.x * blockDim.x + threadIdx.x;
    if (i < N) g_dinv[i] = rsqrtf((float)g_deg[i] + 1.0f);
}
__global__ void fill_kernel(int E) {
    int e = blockIdx.x * blockDim.x + threadIdx.x;
    if (e < E) {
        int d = g_dstE[e];
        int pos = atomicAdd(&g_cursor[d], 1);
        g_csrc[pos] = g_srcE[e];
    }
}

// ---------------- SGEMM: C[M,128] = A[M,128] @ B[128,128], f32x2-packed ----------------
__global__ __launch_bounds__(256, 2)
void gemm_nn128(const float* __restrict__ A, const float* __restrict__ B,
                float* __restrict__ C, int M) {
    __shared__ float As[16][132];   // transposed A tile: As[k][m]
    __shared__ float Bs[16][132];   // Bs[k][n]
    const int tid = threadIdx.x;
    const int tx = tid & 15;        // 16 col groups (8 cols each)
    const int ty = tid >> 4;        // 16 row groups (8 rows each)
    const int row0 = blockIdx.x << 7;

    unsigned long long acc[8][4];
#pragma unroll
    for (int i = 0; i < 8; i++)
#pragma unroll
        for (int j = 0; j < 4; j++) acc[i][j] = 0ull;

    for (int k0 = 0; k0 < 128; k0 += 16) {
        // A tile: 128 rows x 16 cols -> transposed into As
#pragma unroll
        for (int i = 0; i < 2; i++) {
            int f = tid * 2 + i;            // 0..511 (float4 index)
            int r = f >> 2;                 // 0..127
            int c = (f & 3) << 2;           // 0,4,8,12
            float4 v = make_float4(0.f, 0.f, 0.f, 0.f);
            int gr = row0 + r;
            if (gr < M) v = *(const float4*)(A + (size_t)gr * 128 + k0 + c);
            As[c + 0][r] = v.x; As[c + 1][r] = v.y;
            As[c + 2][r] = v.z; As[c + 3][r] = v.w;
        }
        // B tile: 16 rows x 128 cols
#pragma unroll
        for (int i = 0; i < 2; i++) {
            int f = tid * 2 + i;            // 0..511
            int r = f >> 5;                 // 0..15
            int c = (f & 31) << 2;          // 0..124
            *(float4*)(&Bs[r][c]) = *(const float4*)(B + (size_t)(k0 + r) * 128 + c);
        }
        __syncthreads();
#pragma unroll
        for (int kk = 0; kk < 16; kk++) {
            float4 a0 = *(const float4*)(&As[kk][ty * 8]);
            float4 a1 = *(const float4*)(&As[kk][ty * 8 + 4]);
            unsigned long long a2[8];
            a2[0] = dup2(a0.x); a2[1] = dup2(a0.y); a2[2] = dup2(a0.z); a2[3] = dup2(a0.w);
            a2[4] = dup2(a1.x); a2[5] = dup2(a1.y); a2[6] = dup2(a1.z); a2[7] = dup2(a1.w);
            unsigned long long b2[4];
#pragma unroll
            for (int j = 0; j < 4; j++)
                b2[j] = *(const unsigned long long*)(&Bs[kk][tx * 8 + 2 * j]);
#pragma unroll
            for (int i = 0; i < 8; i++)
#pragma unroll
                for (int j = 0; j < 4; j++) fma2(acc[i][j], a2[i], b2[j]);
        }
        __syncthreads();
    }
    // store
#pragma unroll
    for (int i = 0; i < 8; i++) {
        int gr = row0 + ty * 8 + i;
        if (gr < M) {
            float o[8];
#pragma unroll
            for (int j = 0; j < 4; j++) {
                o[2 * j + 0] = __uint_as_float((unsigned)(acc[i][j] & 0xffffffffull));
                o[2 * j + 1] = __uint_as_float((unsigned)(acc[i][j] >> 32));
            }
            *(float4*)(C + (size_t)gr * 128 + tx * 8) = make_float4(o[0], o[1], o[2], o[3]);
            *(float4*)(C + (size_t)gr * 128 + tx * 8 + 4) = make_float4(o[4], o[5], o[6], o[7]);
        }
    }
}

// ---------------- fused aggregate + bias + LayerNorm + ReLU (warp per node) ----------------
__global__ void agg_ln_relu_kernel(const float* __restrict__ cb,
                                   const float* __restrict__ lg,
                                   const float* __restrict__ lb, int N) {
    int n = (blockIdx.x * blockDim.x + threadIdx.x) >> 5;
    int lane = threadIdx.x & 31;
    if (n >= N) return;
    const float4* h4 = (const float4*)g_h;
    float di = g_dinv[n];
    float sl = di * di;
    float4 hv = h4[(size_t)n * 32 + lane];
    float a0 = sl * hv.x, a1 = sl * hv.y, a2 = sl * hv.z, a3 = sl * hv.w;
    int e0 = g_row[n], e1 = g_row[n + 1];
    for (int e = e0; e < e1; e++) {
        int s = g_csrc[e];
        float nrm = g_dinv[s] * di;
        float4 hs = h4[(size_t)s * 32 + lane];
        a0 = fmaf(nrm, hs.x, a0);
        a1 = fmaf(nrm, hs.y, a1);
        a2 = fmaf(nrm, hs.z, a2);
        a3 = fmaf(nrm, hs.w, a3);
    }
    int c = lane * 4;
    a0 += cb[c]; a1 += cb[c + 1]; a2 += cb[c + 2]; a3 += cb[c + 3];
    // mean
    float s = a0 + a1 + a2 + a3;
#pragma unroll
    for (int o = 16; o > 0; o >>= 1) s += __shfl_xor_sync(0xffffffffu, s, o);
    float mu = s * (1.0f / 128.0f);
    float d0 = a0 - mu, d1 = a1 - mu, d2 = a2 - mu, d3 = a3 - mu;
    float v = d0 * d0 + d1 * d1 + d2 * d2 + d3 * d3;
#pragma unroll
    for (int o = 16; o > 0; o >>= 1) v += __shfl_xor_sync(0xffffffffu, v, o);
    float inv = rsqrtf(v * (1.0f / 128.0f) + LNEPS);
    float4 o4;
    o4.x = fmaxf(0.f, fmaf(d0 * inv, lg[c + 0], lb[c + 0]));
    o4.y = fmaxf(0.f, fmaf(d1 * inv, lg[c + 1], lb[c + 1]));
    o4.z = fmaxf(0.f, fmaf(d2 * inv, lg[c + 2], lb[c + 2]));
    o4.w = fmaxf(0.f, fmaf(d3 * inv, lg[c + 3], lb[c + 3]));
    ((float4*)g_act)[(size_t)n * 32 + lane] = o4;
}

// ---------------- output GEMM: out[M,40] = X[M,128] @ W[128,40] + b ----------------
__global__ __launch_bounds__(128)
void out_gemm_kernel(const float* __restrict__ X, const float* __restrict__ Wp,
                     const float* __restrict__ bp, float* __restrict__ out, int M) {
    __shared__ float ws[128 * 40];
    __shared__ float xs[128][33];
    int tid = threadIdx.x;
    int n0 = blockIdx.x << 7;
    for (int i = tid; i < 128 * 40; i += 128) ws[i] = Wp[i];
    float acc[40];
#pragma unroll
    for (int j = 0; j < 40; j++) acc[j] = 0.f;
    for (int kt = 0; kt < 4; kt++) {
        __syncthreads();
#pragma unroll
        for (int i = 0; i < 8; i++) {
            int f = tid + i * 128;      // float4 index 0..1023
            int r = f >> 3;             // 0..127
            int c = (f & 7) << 2;       // 0..28
            float4 v = make_float4(0.f, 0.f, 0.f, 0.f);
            int gr = n0 + r;
            if (gr < M) v = *(const float4*)(X + (size_t)gr * 128 + kt * 32 + c);
            xs[r][c] = v.x; xs[r][c + 1] = v.y; xs[r][c + 2] = v.z; xs[r][c + 3] = v.w;
        }
        __syncthreads();
#pragma unroll
        for (int k = 0; k < 32; k++) {
            float xv = xs[tid][k];
            const float4* w4 = (const float4*)(ws + (size_t)(kt * 32 + k) * 40);
#pragma unroll
            for (int j = 0; j < 10; j++) {
                float4 w = w4[j];
                acc[4 * j + 0] = fmaf(xv, w.x, acc[4 * j + 0]);
                acc[4 * j + 1] = fmaf(xv, w.y, acc[4 * j + 1]);
                acc[4 * j + 2] = fmaf(xv, w.z, acc[4 * j + 2]);
                acc[4 * j + 3] = fmaf(xv, w.w, acc[4 * j + 3]);
            }
        }
    }
    int n = n0 + tid;
    if (n < M) {
#pragma unroll
        for (int j = 0; j < 10; j++) {
            float4 o;
            o.x = acc[4 * j + 0] + bp[4 * j + 0];
            o.y = acc[4 * j + 1] + bp[4 * j + 1];
            o.z = acc[4 * j + 2] + bp[4 * j + 2];
            o.w = acc[4 * j + 3] + bp[4 * j + 3];
            *(float4*)(out + (size_t)n * 40 + 4 * j) = o;
        }
    }
}

// ---------------- launch ----------------
extern "C" void kernel_launch(void* const* d_in, const int* in_sizes, int n_in,
                              void* d_out, int out_size) {
    const float* x      = (const float*)d_in[0];
    const void*  ei     = d_in[1];
    const float* conv_w = (const float*)d_in[2];
    const float* conv_b = (const float*)d_in[3];
    const float* ln_g   = (const float*)d_in[4];
    const float* ln_b   = (const float*)d_in[5];
    const float* wout   = (const float*)d_in[6];
    const float* bout   = (const float*)d_in[7];
    float* out = (float*)d_out;

    const int N = NN;
    const int E = in_sizes[1] / 2;   // element count of edge_index / 2, dtype-independent

    float *hbuf, *abuf;
    cudaGetSymbolAddress((void**)&hbuf, g_h);
    cudaGetSymbolAddress((void**)&abuf, g_act);

    detect_kernel<<<1, 1>>>(ei);
    convert_edges<<<(E + 255) / 256, 256>>>(ei, E);
    zero_deg<<<(N + 255) / 256, 256>>>(N);
    count_kernel<<<(E + 255) / 256, 256>>>(E);
    scan_kernel<<<1, 1024>>>(N);
    dinv_kernel<<<(N + 255) / 256, 256>>>(N);
    fill_kernel<<<(E + 255) / 256, 256>>>(E);

    const float* cur = x;
    for (int l = 0; l < 3; l++) {
        gemm_nn128<<<(N + 127) / 128, 256>>>(cur, conv_w + (size_t)l * 128 * 128, hbuf, N);
        agg_ln_relu_kernel<<<(N + 7) / 8, 256>>>(conv_b + (size_t)l * 128,
                                                 ln_g + (size_t)l * 128,
                                                 ln_b + (size_t)l * 128, N);
        cur = abuf;
    }
    out_gemm_kernel<<<(N + 127) / 128, 128>>>(abuf, wout, bout, out, N);
}

// round 2
// speedup vs baseline: 1.0262x; 1.0262x over previous
#include <cuda_runtime.h>
#include <cstdint>

#define NN 50000
#define EE 800000
#define HIDF 128
#define NCLS 40
#define LNEPS 1e-5f

typedef unsigned long long ull;

// ---------------- scratch (device globals; no allocation allowed) ----------------
__device__ float g_h[(size_t)NN * HIDF];     // post-GEMM features
__device__ float g_act[(size_t)NN * HIDF];   // post-LN activations
__device__ float g_dinv[NN];
__device__ int   g_deg[NN];
__device__ int   g_row[NN + 1];
__device__ int   g_cursor[NN];
__device__ int   g_srcE[EE];
__device__ int   g_dstE[EE];
__device__ int2  g_epack[EE];                // CSR: (src, norm-bits) grouped by dst
__device__ int   g_is64;

// ---------------- f32x2 packed math helpers (sm_103a) ----------------
__device__ __forceinline__ ull dup2(float a) {
    ull r;
    unsigned u = __float_as_uint(a);
    asm("mov.b64 %0, {%1, %1};" : "=l"(r) : "r"(u));
    return r;
}
__device__ __forceinline__ void fma2(ull& d, ull a, ull b) {
    asm("fma.rn.f32x2 %0, %1, %2, %0;" : "+l"(d) : "l"(a), "l"(b));
}
__device__ __forceinline__ ull add2(ull a, ull b) {
    ull r;
    asm("add.rn.f32x2 %0, %1, %2;" : "=l"(r) : "l"(a), "l"(b));
    return r;
}

// ---------------- edge dtype detection ----------------
__global__ void detect_kernel(const void* ei) {
    const long long* p = (const long long*)ei;
    int ok = 1;
#pragma unroll
    for (int i = 0; i < 64; i++) {
        long long v = p[i * 7];   // strided sample
        if (v < 0 || v >= NN) { ok = 0; break; }
    }
    g_is64 = ok;
}

// convert + degree count in one pass
__global__ void convert_count(const void* __restrict__ ei, int E) {
    int e = blockIdx.x * blockDim.x + threadIdx.x;
    if (e >= E) return;
    int s, d;
    if (g_is64) {
        const long long* p = (const long long*)ei;
        s = (int)p[e];
        d = (int)p[E + e];
    } else {
        const int* p = (const int*)ei;
        s = p[e];
        d = p[E + e];
    }
    g_srcE[e] = s;
    g_dstE[e] = d;
    atomicAdd(&g_deg[d], 1);
}

// scan: row offsets + cursor init + dinv, single block
__global__ void scan_kernel(int N) {
    __shared__ int part[1024];
    int tid = threadIdx.x;
    int chunk = (N + 1023) / 1024;
    int b = tid * chunk;
    int e = min(b + chunk, N);
    int s = 0;
    for (int i = b; i < e; i++) s += g_deg[i];
    part[tid] = s;
    __syncthreads();
    for (int off = 1; off < 1024; off <<= 1) {
        int v = (tid >= off) ? part[tid - off] : 0;
        __syncthreads();
        part[tid] += v;
        __syncthreads();
    }
    int run = (tid == 0) ? 0 : part[tid - 1];
    for (int i = b; i < e; i++) {
        int dg = g_deg[i];
        g_row[i] = run;
        g_cursor[i] = run;
        g_dinv[i] = rsqrtf((float)dg + 1.0f);
        run += dg;
    }
    if (tid == 1023) g_row[N] = run;
}

// fill CSR with packed (src, norm)
__global__ void fill_kernel(int E) {
    int e = blockIdx.x * blockDim.x + threadIdx.x;
    if (e < E) {
        int s = g_srcE[e];
        int d = g_dstE[e];
        float nrm = g_dinv[s] * g_dinv[d];
        int pos = atomicAdd(&g_cursor[d], 1);
        g_epack[pos] = make_int2(s, __float_as_int(nrm));
    }
}

// ---------------- SGEMM: C[M,128] = A[M,128] @ B[128,128], f32x2-packed ----------------
// Each thread: 8 M-rows (ty*8..) x 4 column-PAIRS at cols {2*(tx+16j)} (conflict-free LDS)
__global__ __launch_bounds__(256, 2)
void gemm_nn128(const float* __restrict__ A, const float* __restrict__ B,
                float* __restrict__ C, int M) {
    __shared__ float As[32][132];   // As[k][m]
    __shared__ float Bs[32][132];   // Bs[k][n]
    const int tid = threadIdx.x;
    const int tx = tid & 15;
    const int ty = tid >> 4;
    const int row0 = blockIdx.x << 7;

    ull acc[8][4];
#pragma unroll
    for (int i = 0; i < 8; i++)
#pragma unroll
        for (int j = 0; j < 4; j++) acc[i][j] = 0ull;

    for (int k0 = 0; k0 < 128; k0 += 32) {
        // A tile: 128 rows x 32 cols, transposed into As[k][m]
#pragma unroll
        for (int i = 0; i < 4; i++) {
            int f = tid + i * 256;          // float4 index 0..1023
            int r = f >> 3;                 // 0..127
            int c = (f & 7) << 2;           // 0..28
            float4 v = make_float4(0.f, 0.f, 0.f, 0.f);
            int gr = row0 + r;
            if (gr < M) v = *(const float4*)(A + (size_t)gr * 128 + k0 + c);
            As[c + 0][r] = v.x; As[c + 1][r] = v.y;
            As[c + 2][r] = v.z; As[c + 3][r] = v.w;
        }
        // B tile: 32 rows x 128 cols
#pragma unroll
        for (int i = 0; i < 4; i++) {
            int f = tid + i * 256;
            int r = f >> 5;                 // 0..31
            int c = (f & 31) << 2;          // 0..124
            *(float4*)(&Bs[r][c]) = *(const float4*)(B + (size_t)(k0 + r) * 128 + c);
        }
        __syncthreads();
#pragma unroll
        for (int kk = 0; kk < 32; kk++) {
            float4 a0 = *(const float4*)(&As[kk][ty * 8]);
            float4 a1 = *(const float4*)(&As[kk][ty * 8 + 4]);
            ull a2[8];
            a2[0] = dup2(a0.x); a2[1] = dup2(a0.y); a2[2] = dup2(a0.z); a2[3] = dup2(a0.w);
            a2[4] = dup2(a1.x); a2[5] = dup2(a1.y); a2[6] = dup2(a1.z); a2[7] = dup2(a1.w);
            ull b2[4];
#pragma unroll
            for (int j = 0; j < 4; j++)
                b2[j] = *(const ull*)(&Bs[kk][2 * (tx + 16 * j)]);
#pragma unroll
            for (int i = 0; i < 8; i++)
#pragma unroll
                for (int j = 0; j < 4; j++) fma2(acc[i][j], a2[i], b2[j]);
        }
        __syncthreads();
    }
    // store: thread writes col pairs {2tx+32j, +1}
#pragma unroll
    for (int i = 0; i < 8; i++) {
        int gr = row0 + ty * 8 + i;
        if (gr < M) {
#pragma unroll
            for (int j = 0; j < 4; j++)
                *(ull*)(C + (size_t)gr * 128 + 2 * tx + 32 * j) = acc[i][j];
        }
    }
}

// ---------------- fused aggregate + bias + LayerNorm + ReLU (warp per node) ----------------
__global__ void agg_ln_relu_kernel(const float* __restrict__ cb,
                                   const float* __restrict__ lg,
                                   const float* __restrict__ lb, int N) {
    int n = (blockIdx.x * blockDim.x + threadIdx.x) >> 5;
    int lane = threadIdx.x & 31;
    if (n >= N) return;
    const float4* h4 = (const float4*)g_h;
    const int2* ep = g_epack;
    float di = g_dinv[n];
    float sl = di * di;
    float4 hv = h4[(size_t)n * 32 + lane];
    float a0 = sl * hv.x, a1 = sl * hv.y, a2 = sl * hv.z, a3 = sl * hv.w;
    int e = g_row[n], e1 = g_row[n + 1];
    for (; e + 2 <= e1; e += 2) {
        int2 p0 = ep[e];
        int2 p1 = ep[e + 1];
        float4 h0 = h4[(size_t)p0.x * 32 + lane];
        float4 h1 = h4[(size_t)p1.x * 32 + lane];
        float n0 = __int_as_float(p0.y);
        float n1 = __int_as_float(p1.y);
        a0 = fmaf(n0, h0.x, a0); a1 = fmaf(n0, h0.y, a1);
        a2 = fmaf(n0, h0.z, a2); a3 = fmaf(n0, h0.w, a3);
        a0 = fmaf(n1, h1.x, a0); a1 = fmaf(n1, h1.y, a1);
        a2 = fmaf(n1, h1.z, a2); a3 = fmaf(n1, h1.w, a3);
    }
    if (e < e1) {
        int2 p0 = ep[e];
        float4 h0 = h4[(size_t)p0.x * 32 + lane];
        float n0 = __int_as_float(p0.y);
        a0 = fmaf(n0, h0.x, a0); a1 = fmaf(n0, h0.y, a1);
        a2 = fmaf(n0, h0.z, a2); a3 = fmaf(n0, h0.w, a3);
    }
    int c = lane * 4;
    a0 += cb[c]; a1 += cb[c + 1]; a2 += cb[c + 2]; a3 += cb[c + 3];
    float s = a0 + a1 + a2 + a3;
#pragma unroll
    for (int o = 16; o > 0; o >>= 1) s += __shfl_xor_sync(0xffffffffu, s, o);
    float mu = s * (1.0f / 128.0f);
    float d0 = a0 - mu, d1 = a1 - mu, d2 = a2 - mu, d3 = a3 - mu;
    float v = d0 * d0 + d1 * d1 + d2 * d2 + d3 * d3;
#pragma unroll
    for (int o = 16; o > 0; o >>= 1) v += __shfl_xor_sync(0xffffffffu, v, o);
    float inv = rsqrtf(v * (1.0f / 128.0f) + LNEPS);
    float4 o4;
    o4.x = fmaxf(0.f, fmaf(d0 * inv, lg[c + 0], lb[c + 0]));
    o4.y = fmaxf(0.f, fmaf(d1 * inv, lg[c + 1], lb[c + 1]));
    o4.z = fmaxf(0.f, fmaf(d2 * inv, lg[c + 2], lb[c + 2]));
    o4.w = fmaxf(0.f, fmaf(d3 * inv, lg[c + 3], lb[c + 3]));
    ((float4*)g_act)[(size_t)n * 32 + lane] = o4;
}

// ---------------- output GEMM: out[M,40] = X[M,128] @ W[128,40] + b (f32x2) ----------------
__global__ __launch_bounds__(128)
void out_gemm_kernel(const float* __restrict__ X, const float* __restrict__ Wp,
                     const float* __restrict__ bp, float* __restrict__ out, int M) {
    __shared__ float ws[128 * 40];
    __shared__ float xs[128][33];
    int tid = threadIdx.x;
    int n0 = blockIdx.x << 7;
    for (int i = tid; i < 128 * 40; i += 128) ws[i] = Wp[i];
    ull acc[20];
#pragma unroll
    for (int j = 0; j < 20; j++) acc[j] = 0ull;
    for (int kt = 0; kt < 4; kt++) {
        __syncthreads();
#pragma unroll
        for (int i = 0; i < 8; i++) {
            int f = tid + i * 128;
            int r = f >> 3;
            int c = (f & 7) << 2;
            float4 v = make_float4(0.f, 0.f, 0.f, 0.f);
            int gr = n0 + r;
            if (gr < M) v = *(const float4*)(X + (size_t)gr * 128 + kt * 32 + c);
            xs[r][c] = v.x; xs[r][c + 1] = v.y; xs[r][c + 2] = v.z; xs[r][c + 3] = v.w;
        }
        __syncthreads();
#pragma unroll
        for (int k = 0; k < 32; k++) {
            ull xv = dup2(xs[tid][k]);
            const ull* w2 = (const ull*)(ws + (size_t)(kt * 32 + k) * 40);
#pragma unroll
            for (int j = 0; j < 20; j++) fma2(acc[j], xv, w2[j]);
        }
    }
    int n = n0 + tid;
    if (n < M) {
        const ull* b2 = (const ull*)bp;
#pragma unroll
        for (int j = 0; j < 20; j++)
            *(ull*)(out + (size_t)n * 40 + 2 * j) = add2(acc[j], b2[j]);
    }
}

// ---------------- launch ----------------
extern "C" void kernel_launch(void* const* d_in, const int* in_sizes, int n_in,
                              void* d_out, int out_size) {
    const float* x      = (const float*)d_in[0];
    const void*  ei     = d_in[1];
    const float* conv_w = (const float*)d_in[2];
    const float* conv_b = (const float*)d_in[3];
    const float* ln_g   = (const float*)d_in[4];
    const float* ln_b   = (const float*)d_in[5];
    const float* wout   = (const float*)d_in[6];
    const float* bout   = (const float*)d_in[7];
    float* out = (float*)d_out;

    const int N = NN;
    const int E = in_sizes[1] / 2;

    float *hbuf, *abuf;
    int* degp;
    cudaGetSymbolAddress((void**)&hbuf, g_h);
    cudaGetSymbolAddress((void**)&abuf, g_act);
    cudaGetSymbolAddress((void**)&degp, g_deg);

    cudaMemsetAsync(degp, 0, N * sizeof(int));
    detect_kernel<<<1, 1>>>(ei);
    convert_count<<<(E + 255) / 256, 256>>>(ei, E);
    scan_kernel<<<1, 1024>>>(N);
    fill_kernel<<<(E + 255) / 256, 256>>>(E);

    const float* cur = x;
    for (int l = 0; l < 3; l++) {
        gemm_nn128<<<(N + 127) / 128, 256>>>(cur, conv_w + (size_t)l * 128 * 128, hbuf, N);
        agg_ln_relu_kernel<<<(N + 7) / 8, 256>>>(conv_b + (size_t)l * 128,
                                                 ln_g + (size_t)l * 128,
                                                 ln_b + (size_t)l * 128, N);
        cur = abuf;
    }
    out_gemm_kernel<<<(N + 127) / 128, 128>>>(abuf, wout, bout, out, N);
}

// round 3
// speedup vs baseline: 1.3713x; 1.3363x over previous
#include <cuda_runtime.h>
#include <cstdint>

#define NN 50000
#define EE 800000
#define HIDF 128
#define NCLS 40
#define LNEPS 1e-5f

typedef unsigned long long ull;

// ---------------- scratch (device globals; no allocation allowed) ----------------
__device__ float g_h[(size_t)NN * HIDF];     // post-GEMM features
__device__ float g_act[(size_t)NN * HIDF];   // post-LN activations
__device__ float g_dinv[NN];
__device__ int   g_deg[NN];
__device__ int   g_start[NN];                // CSR region start (unordered alloc)
__device__ int   g_srcE[EE];
__device__ int   g_dstE[EE];
__device__ int   g_rank[EE];                 // insertion rank within dst bucket
__device__ int2  g_epack[EE];                // CSR: (src, norm-bits) grouped by dst
__device__ int   g_is64;
__device__ int   g_total;

// ---------------- f32x2 packed math helpers (sm_103a) ----------------
__device__ __forceinline__ ull dup2(float a) {
    ull r;
    unsigned u = __float_as_uint(a);
    asm("mov.b64 %0, {%1, %1};" : "=l"(r) : "r"(u));
    return r;
}
__device__ __forceinline__ void fma2(ull& d, ull a, ull b) {
    asm("fma.rn.f32x2 %0, %1, %2, %0;" : "+l"(d) : "l"(a), "l"(b));
}
__device__ __forceinline__ ull add2(ull a, ull b) {
    ull r;
    asm("add.rn.f32x2 %0, %1, %2;" : "=l"(r) : "l"(a), "l"(b));
    return r;
}

// ---------------- setup: detect dtype + zero counters (one block) ----------------
__global__ void detect_zero_kernel(const void* ei, int N) {
    int tid = threadIdx.x;
    for (int i = tid; i < N; i += 1024) g_deg[i] = 0;
    if (tid == 0) {
        g_total = 0;
        const long long* p = (const long long*)ei;
        int ok = 1;
#pragma unroll
        for (int i = 0; i < 64; i++) {
            long long v = p[i * 7];
            if (v < 0 || v >= NN) { ok = 0; break; }
        }
        g_is64 = ok;
    }
}

// convert + degree count + rank in one pass
__global__ void convert_count(const void* __restrict__ ei, int E) {
    int e = blockIdx.x * blockDim.x + threadIdx.x;
    if (e >= E) return;
    int s, d;
    if (g_is64) {
        const long long* p = (const long long*)ei;
        s = (int)p[e];
        d = (int)p[E + e];
    } else {
        const int* p = (const int*)ei;
        s = p[e];
        d = p[E + e];
    }
    g_srcE[e] = s;
    g_dstE[e] = d;
    g_rank[e] = atomicAdd(&g_deg[d], 1);
}

// unordered CSR region allocation + dinv (block-aggregated atomic)
__global__ void alloc_kernel(int N) {
    __shared__ int warp_sums[32];
    __shared__ int block_base;
    int i = blockIdx.x * blockDim.x + threadIdx.x;
    int lane = threadIdx.x & 31;
    int wid = threadIdx.x >> 5;
    int dg = (i < N) ? g_deg[i] : 0;
    // exclusive prefix within warp
    int pre = dg;
#pragma unroll
    for (int o = 1; o < 32; o <<= 1) {
        int v = __shfl_up_sync(0xffffffffu, pre, o);
        if (lane >= o) pre += v;
    }
    int wtot = __shfl_sync(0xffffffffu, pre, 31);
    int wexc = pre - dg;
    if (lane == 31) warp_sums[wid] = wtot;
    __syncthreads();
    if (wid == 0) {
        int v = (lane < (blockDim.x >> 5)) ? warp_sums[lane] : 0;
        int p = v;
#pragma unroll
        for (int o = 1; o < 32; o <<= 1) {
            int t = __shfl_up_sync(0xffffffffu, p, o);
            if (lane >= o) p += t;
        }
        int btot = __shfl_sync(0xffffffffu, p, 31);
        if (lane == 31) block_base = atomicAdd(&g_total, btot);
        p -= v;  // exclusive
        warp_sums[lane] = p;
    }
    __syncthreads();
    if (i < N) {
        g_start[i] = block_base + warp_sums[wid] + wexc;
        g_dinv[i] = rsqrtf((float)dg + 1.0f);
    }
}

// fill CSR with packed (src, norm): no atomics
__global__ void fill_kernel(int E) {
    int e = blockIdx.x * blockDim.x + threadIdx.x;
    if (e < E) {
        int s = g_srcE[e];
        int d = g_dstE[e];
        float nrm = g_dinv[s] * g_dinv[d];
        int pos = g_start[d] + g_rank[e];
        g_epack[pos] = make_int2(s, __float_as_int(nrm));
    }
}

// ---------------- SGEMM: C[M,128] = A[M,128] @ B[128,128], f32x2, double-buffered ----------------
__global__ __launch_bounds__(256, 2)
void gemm_nn128(const float* __restrict__ A, const float* __restrict__ B,
                float* __restrict__ C, int M) {
    __shared__ float As[2][16][132];   // As[s][k][m]
    __shared__ float Bs[2][16][132];   // Bs[s][k][n]
    const int tid = threadIdx.x;
    const int tx = tid & 15;
    const int ty = tid >> 4;
    const int row0 = blockIdx.x << 7;

    // loader indices (float4 granularity, 512 float4 per tile, 2 per thread)
    const int ar = tid >> 1;                  // A row 0..127
    const int ac = (tid & 1) << 3;            // A col 0/8 (two float4 -> 8 floats? no: 4)
    const int br = tid >> 4;                  // B row 0..15
    const int bc = (tid & 15) << 3;           // B col, 8 floats via 2 float4

    ull acc[8][4];
#pragma unroll
    for (int i = 0; i < 8; i++)
#pragma unroll
        for (int j = 0; j < 4; j++) acc[i][j] = 0ull;

    const bool full = (row0 + 128 <= M);

    // stage load helper via lambda-ish macro
#define LOAD_STAGE(s, k0)                                                        \
    {                                                                            \
        float4 va0, va1;                                                         \
        int gr = row0 + ar;                                                      \
        if (full || gr < M) {                                                    \
            va0 = *(const float4*)(A + (size_t)gr * 128 + (k0) + ac);            \
            va1 = *(const float4*)(A + (size_t)gr * 128 + (k0) + ac + 4);        \
        } else {                                                                 \
            va0 = make_float4(0.f, 0.f, 0.f, 0.f);                               \
            va1 = va0;                                                           \
        }                                                                        \
        float4 vb0 = *(const float4*)(B + (size_t)((k0) + br) * 128 + bc);       \
        float4 vb1 = *(const float4*)(B + (size_t)((k0) + br) * 128 + bc + 4);   \
        As[s][ac + 0][ar] = va0.x; As[s][ac + 1][ar] = va0.y;                    \
        As[s][ac + 2][ar] = va0.z; As[s][ac + 3][ar] = va0.w;                    \
        As[s][ac + 4][ar] = va1.x; As[s][ac + 5][ar] = va1.y;                    \
        As[s][ac + 6][ar] = va1.z; As[s][ac + 7][ar] = va1.w;                    \
        *(float4*)(&Bs[s][br][bc]) = vb0;                                        \
        *(float4*)(&Bs[s][br][bc + 4]) = vb1;                                    \
    }

    LOAD_STAGE(0, 0)
    __syncthreads();

#pragma unroll
    for (int t = 0; t < 8; t++) {
        const int s = t & 1;
        if (t < 7) LOAD_STAGE(s ^ 1, (t + 1) * 16)
#pragma unroll
        for (int kk = 0; kk < 16; kk++) {
            float4 a0 = *(const float4*)(&As[s][kk][ty * 8]);
            float4 a1 = *(const float4*)(&As[s][kk][ty * 8 + 4]);
            ull a2[8];
            a2[0] = dup2(a0.x); a2[1] = dup2(a0.y); a2[2] = dup2(a0.z); a2[3] = dup2(a0.w);
            a2[4] = dup2(a1.x); a2[5] = dup2(a1.y); a2[6] = dup2(a1.z); a2[7] = dup2(a1.w);
            ull b2[4];
#pragma unroll
            for (int j = 0; j < 4; j++)
                b2[j] = *(const ull*)(&Bs[s][kk][2 * (tx + 16 * j)]);
#pragma unroll
            for (int i = 0; i < 8; i++)
#pragma unroll
                for (int j = 0; j < 4; j++) fma2(acc[i][j], a2[i], b2[j]);
        }
        __syncthreads();
    }
#undef LOAD_STAGE

#pragma unroll
    for (int i = 0; i < 8; i++) {
        int gr = row0 + ty * 8 + i;
        if (full || gr < M) {
#pragma unroll
            for (int j = 0; j < 4; j++)
                *(ull*)(C + (size_t)gr * 128 + 2 * tx + 32 * j) = acc[i][j];
        }
    }
}

// ---------------- fused aggregate + bias + LayerNorm + ReLU (warp per node) ----------------
__global__ void agg_ln_relu_kernel(const float* __restrict__ cb,
                                   const float* __restrict__ lg,
                                   const float* __restrict__ lb, int N) {
    int n = (blockIdx.x * blockDim.x + threadIdx.x) >> 5;
    int lane = threadIdx.x & 31;
    if (n >= N) return;
    const float4* h4 = (const float4*)g_h;
    const int2* ep = g_epack;
    float di = g_dinv[n];
    float sl = di * di;
    float4 hv = h4[(size_t)n * 32 + lane];
    float a0 = sl * hv.x, a1 = sl * hv.y, a2 = sl * hv.z, a3 = sl * hv.w;
    int e = g_start[n];
    int e1 = e + g_deg[n];
    for (; e + 4 <= e1; e += 4) {
        int2 p0 = ep[e];
        int2 p1 = ep[e + 1];
        int2 p2 = ep[e + 2];
        int2 p3 = ep[e + 3];
        float4 h0 = h4[(size_t)p0.x * 32 + lane];
        float4 h1 = h4[(size_t)p1.x * 32 + lane];
        float4 h2 = h4[(size_t)p2.x * 32 + lane];
        float4 h3 = h4[(size_t)p3.x * 32 + lane];
        float n0 = __int_as_float(p0.y), n1 = __int_as_float(p1.y);
        float n2 = __int_as_float(p2.y), n3 = __int_as_float(p3.y);
        a0 = fmaf(n0, h0.x, a0); a1 = fmaf(n0, h0.y, a1);
        a2 = fmaf(n0, h0.z, a2); a3 = fmaf(n0, h0.w, a3);
        a0 = fmaf(n1, h1.x, a0); a1 = fmaf(n1, h1.y, a1);
        a2 = fmaf(n1, h1.z, a2); a3 = fmaf(n1, h1.w, a3);
        a0 = fmaf(n2, h2.x, a0); a1 = fmaf(n2, h2.y, a1);
        a2 = fmaf(n2, h2.z, a2); a3 = fmaf(n2, h2.w, a3);
        a0 = fmaf(n3, h3.x, a0); a1 = fmaf(n3, h3.y, a1);
        a2 = fmaf(n3, h3.z, a2); a3 = fmaf(n3, h3.w, a3);
    }
    for (; e < e1; e++) {
        int2 p0 = ep[e];
        float4 h0 = h4[(size_t)p0.x * 32 + lane];
        float n0 = __int_as_float(p0.y);
        a0 = fmaf(n0, h0.x, a0); a1 = fmaf(n0, h0.y, a1);
        a2 = fmaf(n0, h0.z, a2); a3 = fmaf(n0, h0.w, a3);
    }
    int c = lane * 4;
    a0 += cb[c]; a1 += cb[c + 1]; a2 += cb[c + 2]; a3 += cb[c + 3];
    float s = a0 + a1 + a2 + a3;
#pragma unroll
    for (int o = 16; o > 0; o >>= 1) s += __shfl_xor_sync(0xffffffffu, s, o);
    float mu = s * (1.0f / 128.0f);
    float d0 = a0 - mu, d1 = a1 - mu, d2 = a2 - mu, d3 = a3 - mu;
    float v = d0 * d0 + d1 * d1 + d2 * d2 + d3 * d3;
#pragma unroll
    for (int o = 16; o > 0; o >>= 1) v += __shfl_xor_sync(0xffffffffu, v, o);
    float inv = rsqrtf(v * (1.0f / 128.0f) + LNEPS);
    float4 o4;
    o4.x = fmaxf(0.f, fmaf(d0 * inv, lg[c + 0], lb[c + 0]));
    o4.y = fmaxf(0.f, fmaf(d1 * inv, lg[c + 1], lb[c + 1]));
    o4.z = fmaxf(0.f, fmaf(d2 * inv, lg[c + 2], lb[c + 2]));
    o4.w = fmaxf(0.f, fmaf(d3 * inv, lg[c + 3], lb[c + 3]));
    ((float4*)g_act)[(size_t)n * 32 + lane] = o4;
}

// ---------------- output GEMM: out[M,40] = X[M,128] @ W[128,40] + b (f32x2) ----------------
__global__ __launch_bounds__(128)
void out_gemm_kernel(const float* __restrict__ X, const float* __restrict__ Wp,
                     const float* __restrict__ bp, float* __restrict__ out, int M) {
    __shared__ float ws[128 * 40];
    __shared__ float xs[128][33];
    int tid = threadIdx.x;
    int n0 = blockIdx.x << 7;
    for (int i = tid; i < 128 * 40; i += 128) ws[i] = Wp[i];
    ull acc[20];
#pragma unroll
    for (int j = 0; j < 20; j++) acc[j] = 0ull;
    for (int kt = 0; kt < 4; kt++) {
        __syncthreads();
#pragma unroll
        for (int i = 0; i < 8; i++) {
            int f = tid + i * 128;
            int r = f >> 3;
            int c = (f & 7) << 2;
            float4 v = make_float4(0.f, 0.f, 0.f, 0.f);
            int gr = n0 + r;
            if (gr < M) v = *(const float4*)(X + (size_t)gr * 128 + kt * 32 + c);
            xs[r][c] = v.x; xs[r][c + 1] = v.y; xs[r][c + 2] = v.z; xs[r][c + 3] = v.w;
        }
        __syncthreads();
#pragma unroll
        for (int k = 0; k < 32; k++) {
            ull xv = dup2(xs[tid][k]);
            const ull* w2 = (const ull*)(ws + (size_t)(kt * 32 + k) * 40);
#pragma unroll
            for (int j = 0; j < 20; j++) fma2(acc[j], xv, w2[j]);
        }
    }
    int n = n0 + tid;
    if (n < M) {
        const ull* b2 = (const ull*)bp;
#pragma unroll
        for (int j = 0; j < 20; j++)
            *(ull*)(out + (size_t)n * 40 + 2 * j) = add2(acc[j], b2[j]);
    }
}

// ---------------- launch ----------------
extern "C" void kernel_launch(void* const* d_in, const int* in_sizes, int n_in,
                              void* d_out, int out_size) {
    const float* x      = (const float*)d_in[0];
    const void*  ei     = d_in[1];
    const float* conv_w = (const float*)d_in[2];
    const float* conv_b = (const float*)d_in[3];
    const float* ln_g   = (const float*)d_in[4];
    const float* ln_b   = (const float*)d_in[5];
    const float* wout   = (const float*)d_in[6];
    const float* bout   = (const float*)d_in[7];
    float* out = (float*)d_out;

    const int N = NN;
    const int E = in_sizes[1] / 2;

    float *hbuf, *abuf;
    cudaGetSymbolAddress((void**)&hbuf, g_h);
    cudaGetSymbolAddress((void**)&abuf, g_act);

    detect_zero_kernel<<<1, 1024>>>(ei, N);
    convert_count<<<(E + 255) / 256, 256>>>(ei, E);
    alloc_kernel<<<(N + 1023) / 1024, 1024>>>(N);
    fill_kernel<<<(E + 255) / 256, 256>>>(E);

    const float* cur = x;
    for (int l = 0; l < 3; l++) {
        gemm_nn128<<<(N + 127) / 128, 256>>>(cur, conv_w + (size_t)l * 128 * 128, hbuf, N);
        agg_ln_relu_kernel<<<(N + 7) / 8, 256>>>(conv_b + (size_t)l * 128,
                                                 ln_g + (size_t)l * 128,
                                                 ln_b + (size_t)l * 128, N);
        cur = abuf;
    }
    out_gemm_kernel<<<(N + 127) / 128, 128>>>(abuf, wout, bout, out, N);
}

// round 4
// speedup vs baseline: 1.6329x; 1.1908x over previous
#include <cuda_runtime.h>
#include <cuda_fp16.h>
#include <cstdint>

#define NN 50000
#define EE 800000
#define HIDF 128
#define NCLS 40
#define LNEPS 1e-5f

typedef unsigned long long ull;

// ---------------- scratch (device globals; no allocation allowed) ----------------
__device__ __half2 g_h16[(size_t)NN * 64];   // pre-scaled post-GEMM features, fp16 pairs
__device__ float g_act[(size_t)NN * HIDF];   // post-LN activations (fp32)
__device__ float g_dinv[NN];
__device__ int   g_deg[NN];
__device__ int   g_start[NN];                // CSR region start (unordered alloc)
__device__ int   g_rank[EE];                 // insertion rank within dst bucket
__device__ int   g_csrc[EE];                 // CSR src ids grouped by dst
__device__ int   g_is64;
__device__ int   g_total;

// ---------------- f32x2 packed math helpers (sm_103a) ----------------
__device__ __forceinline__ ull dup2(float a) {
    ull r;
    unsigned u = __float_as_uint(a);
    asm("mov.b64 %0, {%1, %1};" : "=l"(r) : "r"(u));
    return r;
}
__device__ __forceinline__ void fma2(ull& d, ull a, ull b) {
    asm("fma.rn.f32x2 %0, %1, %2, %0;" : "+l"(d) : "l"(a), "l"(b));
}
__device__ __forceinline__ ull add2(ull a, ull b) {
    ull r;
    asm("add.rn.f32x2 %0, %1, %2;" : "=l"(r) : "l"(a), "l"(b));
    return r;
}

// ---------------- setup: detect dtype + zero counters (one block) ----------------
__global__ void detect_zero_kernel(const void* ei, int N) {
    int tid = threadIdx.x;
    for (int i = tid; i < N; i += 1024) g_deg[i] = 0;
    if (tid == 0) {
        g_total = 0;
        const long long* p = (const long long*)ei;
        int ok = 1;
#pragma unroll
        for (int i = 0; i < 64; i++) {
            long long v = p[i * 7];
            if (v < 0 || v >= NN) { ok = 0; break; }
        }
        g_is64 = ok;
    }
}

// degree count + rank in one pass (no src/dst materialization)
__global__ void convert_count(const void* __restrict__ ei, int E) {
    int e = blockIdx.x * blockDim.x + threadIdx.x;
    if (e >= E) return;
    int d;
    if (g_is64) {
        const long long* p = (const long long*)ei;
        d = (int)p[E + e];
    } else {
        const int* p = (const int*)ei;
        d = p[E + e];
    }
    g_rank[e] = atomicAdd(&g_deg[d], 1);
}

// unordered CSR region allocation + dinv (block-aggregated atomic)
__global__ void alloc_kernel(int N) {
    __shared__ int warp_sums[32];
    __shared__ int block_base;
    int i = blockIdx.x * blockDim.x + threadIdx.x;
    int lane = threadIdx.x & 31;
    int wid = threadIdx.x >> 5;
    int dg = (i < N) ? g_deg[i] : 0;
    int pre = dg;
#pragma unroll
    for (int o = 1; o < 32; o <<= 1) {
        int v = __shfl_up_sync(0xffffffffu, pre, o);
        if (lane >= o) pre += v;
    }
    int wtot = __shfl_sync(0xffffffffu, pre, 31);
    int wexc = pre - dg;
    if (lane == 31) warp_sums[wid] = wtot;
    __syncthreads();
    if (wid == 0) {
        int v = (lane < (blockDim.x >> 5)) ? warp_sums[lane] : 0;
        int p = v;
#pragma unroll
        for (int o = 1; o < 32; o <<= 1) {
            int t = __shfl_up_sync(0xffffffffu, p, o);
            if (lane >= o) p += t;
        }
        int btot = __shfl_sync(0xffffffffu, p, 31);
        if (lane == 31) block_base = atomicAdd(&g_total, btot);
        p -= v;
        warp_sums[lane] = p;
    }
    __syncthreads();
    if (i < N) {
        g_start[i] = block_base + warp_sums[wid] + wexc;
        g_dinv[i] = rsqrtf((float)dg + 1.0f);
    }
}

// fill CSR (src only): no atomics
__global__ void fill_kernel(const void* __restrict__ ei, int E) {
    int e = blockIdx.x * blockDim.x + threadIdx.x;
    if (e >= E) return;
    int s, d;
    if (g_is64) {
        const long long* p = (const long long*)ei;
        s = (int)p[e];
        d = (int)p[E + e];
    } else {
        const int* p = (const int*)ei;
        s = p[e];
        d = p[E + e];
    }
    g_csrc[g_start[d] + g_rank[e]] = s;
}

// ---------------- SGEMM: h16[M,64] = half2(dinv[m] * (A[M,128] @ B[128,128])) ----------------
__global__ __launch_bounds__(256, 2)
void gemm_nn128(const float* __restrict__ A, const float* __restrict__ B, int M) {
    __shared__ float As[2][16][132];
    __shared__ float Bs[2][16][132];
    const int tid = threadIdx.x;
    const int tx = tid & 15;
    const int ty = tid >> 4;
    const int row0 = blockIdx.x << 7;

    const int ar = tid >> 1;
    const int ac = (tid & 1) << 3;
    const int br = tid >> 4;
    const int bc = (tid & 15) << 3;

    ull acc[8][4];
#pragma unroll
    for (int i = 0; i < 8; i++)
#pragma unroll
        for (int j = 0; j < 4; j++) acc[i][j] = 0ull;

    const bool full = (row0 + 128 <= M);

#define LOAD_STAGE(s, k0)                                                        \
    {                                                                            \
        float4 va0, va1;                                                         \
        int gr = row0 + ar;                                                      \
        if (full || gr < M) {                                                    \
            va0 = *(const float4*)(A + (size_t)gr * 128 + (k0) + ac);            \
            va1 = *(const float4*)(A + (size_t)gr * 128 + (k0) + ac + 4);        \
        } else {                                                                 \
            va0 = make_float4(0.f, 0.f, 0.f, 0.f);                               \
            va1 = va0;                                                           \
        }                                                                        \
        float4 vb0 = *(const float4*)(B + (size_t)((k0) + br) * 128 + bc);       \
        float4 vb1 = *(const float4*)(B + (size_t)((k0) + br) * 128 + bc + 4);   \
        As[s][ac + 0][ar] = va0.x; As[s][ac + 1][ar] = va0.y;                    \
        As[s][ac + 2][ar] = va0.z; As[s][ac + 3][ar] = va0.w;                    \
        As[s][ac + 4][ar] = va1.x; As[s][ac + 5][ar] = va1.y;                    \
        As[s][ac + 6][ar] = va1.z; As[s][ac + 7][ar] = va1.w;                    \
        *(float4*)(&Bs[s][br][bc]) = vb0;                                        \
        *(float4*)(&Bs[s][br][bc + 4]) = vb1;                                    \
    }

    LOAD_STAGE(0, 0)
    __syncthreads();

#pragma unroll
    for (int t = 0; t < 8; t++) {
        const int s = t & 1;
        if (t < 7) LOAD_STAGE(s ^ 1, (t + 1) * 16)
#pragma unroll
        for (int kk = 0; kk < 16; kk++) {
            float4 a0 = *(const float4*)(&As[s][kk][ty * 8]);
            float4 a1 = *(const float4*)(&As[s][kk][ty * 8 + 4]);
            ull a2[8];
            a2[0] = dup2(a0.x); a2[1] = dup2(a0.y); a2[2] = dup2(a0.z); a2[3] = dup2(a0.w);
            a2[4] = dup2(a1.x); a2[5] = dup2(a1.y); a2[6] = dup2(a1.z); a2[7] = dup2(a1.w);
            ull b2[4];
#pragma unroll
            for (int j = 0; j < 4; j++)
                b2[j] = *(const ull*)(&Bs[s][kk][2 * (tx + 16 * j)]);
#pragma unroll
            for (int i = 0; i < 8; i++)
#pragma unroll
                for (int j = 0; j < 4; j++) fma2(acc[i][j], a2[i], b2[j]);
        }
        __syncthreads();
    }
#undef LOAD_STAGE

    // epilogue: scale by dinv[row], convert to half2, store to g_h16
#pragma unroll
    for (int i = 0; i < 8; i++) {
        int gr = row0 + ty * 8 + i;
        if (full || gr < M) {
            float di = g_dinv[gr];
#pragma unroll
            for (int j = 0; j < 4; j++) {
                float c0 = __uint_as_float((unsigned)(acc[i][j] & 0xffffffffull)) * di;
                float c1 = __uint_as_float((unsigned)(acc[i][j] >> 32)) * di;
                g_h16[(size_t)gr * 64 + tx + 16 * j] = __floats2half2_rn(c0, c1);
            }
        }
    }
}

// ---------------- fused aggregate + bias + LayerNorm + ReLU (warp per node) ----------------
// agg[n] = dinv[n] * ( sum_nb h16[s] + h16[n] ) + bias ; then LN ; then ReLU
__global__ void agg_ln_relu_kernel(const float* __restrict__ cb,
                                   const float* __restrict__ lg,
                                   const float* __restrict__ lb, int N) {
    int n = (blockIdx.x * blockDim.x + threadIdx.x) >> 5;
    int lane = threadIdx.x & 31;
    if (n >= N) return;
    const int* __restrict__ cs = g_csrc;
    // lane covers features 4*lane..4*lane+3 = half2 pairs {2*lane, 2*lane+1} = one 8B load
    const ull* __restrict__ hrow = (const ull*)g_h16 + lane;   // + 32*src per row

    float a0, a1, a2, a3;
    {   // self term
        ull v = hrow[(size_t)n * 32];
        __half2 p0 = *(__half2*)&v;
        __half2 p1 = *((__half2*)&v + 1);
        float2 f0 = __half22float2(p0);
        float2 f1 = __half22float2(p1);
        a0 = f0.x; a1 = f0.y; a2 = f1.x; a3 = f1.y;
    }
    int e = g_start[n];
    int e1 = e + g_deg[n];
    for (; e + 4 <= e1; e += 4) {
        int s0 = cs[e], s1 = cs[e + 1], s2 = cs[e + 2], s3 = cs[e + 3];
        ull v0 = hrow[(size_t)s0 * 32];
        ull v1 = hrow[(size_t)s1 * 32];
        ull v2 = hrow[(size_t)s2 * 32];
        ull v3 = hrow[(size_t)s3 * 32];
#define ACC(v)                                                   \
        {                                                        \
            float2 f0 = __half22float2(*(__half2*)&(v));         \
            float2 f1 = __half22float2(*((__half2*)&(v) + 1));   \
            a0 += f0.x; a1 += f0.y; a2 += f1.x; a3 += f1.y;      \
        }
        ACC(v0) ACC(v1) ACC(v2) ACC(v3)
    }
    for (; e < e1; e++) {
        ull v = hrow[(size_t)cs[e] * 32];
        ACC(v)
    }
#undef ACC
    float di = g_dinv[n];
    int c = lane * 4;
    a0 = fmaf(di, a0, cb[c]);
    a1 = fmaf(di, a1, cb[c + 1]);
    a2 = fmaf(di, a2, cb[c + 2]);
    a3 = fmaf(di, a3, cb[c + 3]);
    float s = a0 + a1 + a2 + a3;
#pragma unroll
    for (int o = 16; o > 0; o >>= 1) s += __shfl_xor_sync(0xffffffffu, s, o);
    float mu = s * (1.0f / 128.0f);
    float d0 = a0 - mu, d1 = a1 - mu, d2 = a2 - mu, d3 = a3 - mu;
    float v = d0 * d0 + d1 * d1 + d2 * d2 + d3 * d3;
#pragma unroll
    for (int o = 16; o > 0; o >>= 1) v += __shfl_xor_sync(0xffffffffu, v, o);
    float inv = rsqrtf(v * (1.0f / 128.0f) + LNEPS);
    float4 o4;
    o4.x = fmaxf(0.f, fmaf(d0 * inv, lg[c + 0], lb[c + 0]));
    o4.y = fmaxf(0.f, fmaf(d1 * inv, lg[c + 1], lb[c + 1]));
    o4.z = fmaxf(0.f, fmaf(d2 * inv, lg[c + 2], lb[c + 2]));
    o4.w = fmaxf(0.f, fmaf(d3 * inv, lg[c + 3], lb[c + 3]));
    ((float4*)g_act)[(size_t)n * 32 + lane] = o4;
}

// ---------------- output GEMM: out[M,40] = X[M,128] @ W[128,40] + b (f32x2) ----------------
__global__ __launch_bounds__(128)
void out_gemm_kernel(const float* __restrict__ X, const float* __restrict__ Wp,
                     const float* __restrict__ bp, float* __restrict__ out, int M) {
    __shared__ float ws[128 * 40];
    __shared__ float xs[128][33];
    int tid = threadIdx.x;
    int n0 = blockIdx.x << 7;
    for (int i = tid; i < 128 * 40; i += 128) ws[i] = Wp[i];
    ull acc[20];
#pragma unroll
    for (int j = 0; j < 20; j++) acc[j] = 0ull;
    for (int kt = 0; kt < 4; kt++) {
        __syncthreads();
#pragma unroll
        for (int i = 0; i < 8; i++) {
            int f = tid + i * 128;
            int r = f >> 3;
            int c = (f & 7) << 2;
            float4 v = make_float4(0.f, 0.f, 0.f, 0.f);
            int gr = n0 + r;
            if (gr < M) v = *(const float4*)(X + (size_t)gr * 128 + kt * 32 + c);
            xs[r][c] = v.x; xs[r][c + 1] = v.y; xs[r][c + 2] = v.z; xs[r][c + 3] = v.w;
        }
        __syncthreads();
#pragma unroll
        for (int k = 0; k < 32; k++) {
            ull xv = dup2(xs[tid][k]);
            const ull* w2 = (const ull*)(ws + (size_t)(kt * 32 + k) * 40);
#pragma unroll
            for (int j = 0; j < 20; j++) fma2(acc[j], xv, w2[j]);
        }
    }
    int n = n0 + tid;
    if (n < M) {
        const ull* b2 = (const ull*)bp;
#pragma unroll
        for (int j = 0; j < 20; j++)
            *(ull*)(out + (size_t)n * 40 + 2 * j) = add2(acc[j], b2[j]);
    }
}

// ---------------- launch ----------------
extern "C" void kernel_launch(void* const* d_in, const int* in_sizes, int n_in,
                              void* d_out, int out_size) {
    const float* x      = (const float*)d_in[0];
    const void*  ei     = d_in[1];
    const float* conv_w = (const float*)d_in[2];
    const float* conv_b = (const float*)d_in[3];
    const float* ln_g   = (const float*)d_in[4];
    const float* ln_b   = (const float*)d_in[5];
    const float* wout   = (const float*)d_in[6];
    const float* bout   = (const float*)d_in[7];
    float* out = (float*)d_out;

    const int N = NN;
    const int E = in_sizes[1] / 2;

    float* abuf;
    cudaGetSymbolAddress((void**)&abuf, g_act);

    detect_zero_kernel<<<1, 1024>>>(ei, N);
    convert_count<<<(E + 255) / 256, 256>>>(ei, E);
    alloc_kernel<<<(N + 1023) / 1024, 1024>>>(N);
    fill_kernel<<<(E + 255) / 256, 256>>>(ei, E);

    const float* cur = x;
    for (int l = 0; l < 3; l++) {
        gemm_nn128<<<(N + 127) / 128, 256>>>(cur, conv_w + (size_t)l * 128 * 128, N);
        agg_ln_relu_kernel<<<(N + 7) / 8, 256>>>(conv_b + (size_t)l * 128,
                                                 ln_g + (size_t)l * 128,
                                                 ln_b + (size_t)l * 128, N);
        cur = abuf;
    }
    out_gemm_kernel<<<(N + 127) / 128, 128>>>(abuf, wout, bout, out, N);
}

// round 6
// speedup vs baseline: 1.9758x; 1.2100x over previous
#include <cuda_runtime.h>
#include <cuda_fp16.h>
#include <cstdint>

#define NN 50000
#define EE 800000
#define HIDF 128
#define NCLS 40
#define LNEPS 1e-5f
#define PADH 136   // halves per smem row (272B): ldmatrix conflict-free (17 mod 8 = 1)

typedef unsigned long long ull;

// ---------------- scratch (device globals; no allocation allowed) ----------------
__device__ __half2 g_h16[(size_t)NN * 64];   // pre-scaled post-GEMM features, fp16 pairs
__device__ float g_act[(size_t)NN * HIDF];   // post-LN activations (fp32)
__device__ float g_dinv[NN];
__device__ int   g_deg[NN];
__device__ int   g_start[NN];
__device__ int   g_rank[EE];
__device__ int   g_csrc[EE];
__device__ int   g_is64;
__device__ int   g_total;
__device__ ull   g_wpkh[12288];              // fp16 hi(W^T): [l][n][k], row-major
__device__ ull   g_wpkl[12288];              // fp16 lo(W^T)

// ---------------- f32x2 packed math helpers (sm_103a base ok) ----------------
__device__ __forceinline__ ull dup2(float a) {
    ull r;
    unsigned u = __float_as_uint(a);
    asm("mov.b64 %0, {%1, %1};" : "=l"(r) : "r"(u));
    return r;
}
__device__ __forceinline__ void fma2(ull& d, ull a, ull b) {
    asm("fma.rn.f32x2 %0, %1, %2, %0;" : "+l"(d) : "l"(a), "l"(b));
}
__device__ __forceinline__ ull add2(ull a, ull b) {
    ull r;
    asm("add.rn.f32x2 %0, %1, %2;" : "=l"(r) : "l"(a), "l"(b));
    return r;
}

__device__ __forceinline__ uint32_t smem_u32(const void* p) {
    uint32_t a;
    asm("{ .reg .u64 t; cvta.to.shared.u64 t, %1; cvt.u32.u64 %0, t; }" : "=r"(a) : "l"(p));
    return a;
}

// ---------------- HMMA helpers ----------------
__device__ __forceinline__ void mma16816(float* c, const uint32_t* a, const uint32_t* b) {
    asm volatile(
        "mma.sync.aligned.m16n8k16.row.col.f32.f16.f16.f32 "
        "{%0,%1,%2,%3}, {%4,%5,%6,%7}, {%8,%9}, {%0,%1,%2,%3};"
        : "+f"(c[0]), "+f"(c[1]), "+f"(c[2]), "+f"(c[3])
        : "r"(a[0]), "r"(a[1]), "r"(a[2]), "r"(a[3]), "r"(b[0]), "r"(b[1]));
}
__device__ __forceinline__ void ldmx4(uint32_t* r, const __half* p) {
    uint32_t a = smem_u32(p);
    asm volatile("ldmatrix.sync.aligned.m8n8.x4.shared.b16 {%0,%1,%2,%3}, [%4];"
                 : "=r"(r[0]), "=r"(r[1]), "=r"(r[2]), "=r"(r[3]) : "r"(a));
}

// ---------------- setup kernels ----------------
__global__ void detect_zero_kernel(const void* ei, int N) {
    int tid = threadIdx.x;
    for (int i = tid; i < N; i += 1024) g_deg[i] = 0;
    if (tid == 0) {
        g_total = 0;
        const long long* p = (const long long*)ei;
        int ok = 1;
#pragma unroll
        for (int i = 0; i < 64; i++) {
            long long v = p[i * 7];
            if (v < 0 || v >= NN) { ok = 0; break; }
        }
        g_is64 = ok;
    }
}

__global__ void convert_count(const void* __restrict__ ei, int E) {
    int e = blockIdx.x * blockDim.x + threadIdx.x;
    if (e >= E) return;
    int d;
    if (g_is64) {
        const long long* p = (const long long*)ei;
        d = (int)p[E + e];
    } else {
        const int* p = (const int*)ei;
        d = p[E + e];
    }
    g_rank[e] = atomicAdd(&g_deg[d], 1);
}

__global__ void alloc_kernel(int N) {
    __shared__ int warp_sums[32];
    __shared__ int block_base;
    int i = blockIdx.x * blockDim.x + threadIdx.x;
    int lane = threadIdx.x & 31;
    int wid = threadIdx.x >> 5;
    int dg = (i < N) ? g_deg[i] : 0;
    int pre = dg;
#pragma unroll
    for (int o = 1; o < 32; o <<= 1) {
        int v = __shfl_up_sync(0xffffffffu, pre, o);
        if (lane >= o) pre += v;
    }
    int wtot = __shfl_sync(0xffffffffu, pre, 31);
    int wexc = pre - dg;
    if (lane == 31) warp_sums[wid] = wtot;
    __syncthreads();
    if (wid == 0) {
        int v = (lane < (blockDim.x >> 5)) ? warp_sums[lane] : 0;
        int p = v;
#pragma unroll
        for (int o = 1; o < 32; o <<= 1) {
            int t = __shfl_up_sync(0xffffffffu, p, o);
            if (lane >= o) p += t;
        }
        int btot = __shfl_sync(0xffffffffu, p, 31);
        if (lane == 31) block_base = atomicAdd(&g_total, btot);
        p -= v;
        warp_sums[lane] = p;
    }
    __syncthreads();
    if (i < N) {
        g_start[i] = block_base + warp_sums[wid] + wexc;
        g_dinv[i] = rsqrtf((float)dg + 1.0f);
    }
}

__global__ void fill_kernel(const void* __restrict__ ei, int E) {
    int e = blockIdx.x * blockDim.x + threadIdx.x;
    if (e >= E) return;
    int s, d;
    if (g_is64) {
        const long long* p = (const long long*)ei;
        s = (int)p[e];
        d = (int)p[E + e];
    } else {
        const int* p = (const int*)ei;
        s = p[e];
        d = p[E + e];
    }
    g_csrc[g_start[d] + g_rank[e]] = s;
}

// pack conv weights: Wh/Wl[l][n][k] = hi/lo fp16 of w[l][k][n]
__global__ void wprep_kernel(const float* __restrict__ cw) {
    int e = blockIdx.x * blockDim.x + threadIdx.x;
    if (e >= 3 * 16384) return;
    int l = e >> 14;
    int r = e & 16383;
    int k = r >> 7;
    int n = r & 127;
    float w = cw[e];
    __half h = __float2half_rn(w);
    __half lo = __float2half_rn(w - __half2float(h));
    size_t off = (size_t)l * 16384 + (size_t)n * 128 + k;
    ((__half*)g_wpkh)[off] = h;
    ((__half*)g_wpkl)[off] = lo;
}

// ---------------- HMMA GEMM: h16 = half2(dinv[m] * (A[M,128] @ W[128,128])) ----------------
// D = Ah@Bh + Ah@Bl + Al@Bh  (A = Ah+Al fp16 split, B = W^T = Bh+Bl fp16 split)
__global__ __launch_bounds__(256, 1)
void gemm_hmma(const float* __restrict__ A, int layer, int M) {
    extern __shared__ __half sm[];
    __half* sAh = sm;
    __half* sAl = sm + 128 * PADH;
    __half* sBh = sm + 2 * 128 * PADH;
    __half* sBl = sm + 3 * 128 * PADH;
    const int tid = threadIdx.x;
    const int wid = tid >> 5;
    const int lane = tid & 31;
    const int row0 = blockIdx.x << 7;

    // ---- copy B (packed fp16 [n][k]) into padded smem ----
    {
        const float4* wh = (const float4*)g_wpkh + (size_t)layer * 2048;
        const float4* wl = (const float4*)g_wpkl + (size_t)layer * 2048;
#pragma unroll
        for (int i = 0; i < 8; i++) {
            int idx = tid + 256 * i;        // float4(8 halves) idx, 16 per row
            int n = idx >> 4;
            int c8 = (idx & 15) << 3;
            *(float4*)(sBh + n * PADH + c8) = wh[idx];
            *(float4*)(sBl + n * PADH + c8) = wl[idx];
        }
    }
    // ---- load + split A: fp32 -> Ah/Al fp16 ----
    {
#pragma unroll
        for (int i = 0; i < 16; i++) {
            int idx = tid + 256 * i;        // float4 idx, 32 per row
            int m = idx >> 5;
            int c4 = (idx & 31) << 2;
            float4 v = make_float4(0.f, 0.f, 0.f, 0.f);
            int gr = row0 + m;
            if (gr < M) v = *(const float4*)(A + (size_t)gr * 128 + c4);
            __half h0 = __float2half_rn(v.x), h1 = __float2half_rn(v.y);
            __half h2 = __float2half_rn(v.z), h3 = __float2half_rn(v.w);
            __half l0 = __float2half_rn(v.x - __half2float(h0));
            __half l1 = __float2half_rn(v.y - __half2float(h1));
            __half l2 = __float2half_rn(v.z - __half2float(h2));
            __half l3 = __float2half_rn(v.w - __half2float(h3));
            __half* ph = sAh + m * PADH + c4;
            __half* pl = sAl + m * PADH + c4;
            *(__half2*)(ph) = __halves2half2(h0, h1);
            *(__half2*)(ph + 2) = __halves2half2(h2, h3);
            *(__half2*)(pl) = __halves2half2(l0, l1);
            *(__half2*)(pl + 2) = __halves2half2(l2, l3);
        }
    }
    __syncthreads();

    // ---- warp tiling: 4(m) x 2(n); warp tile 32 x 64 ----
    const int wm = wid & 3;
    const int wn = wid >> 2;
    float acc[2][8][4];
#pragma unroll
    for (int mt = 0; mt < 2; mt++)
#pragma unroll
        for (int nt = 0; nt < 8; nt++)
#pragma unroll
            for (int j = 0; j < 4; j++) acc[mt][nt][j] = 0.f;

    // ldmatrix lane addressing
    const int a_r = lane & 15;              // A row within 16
    const int a_c = (lane >> 4) << 3;       // A k-offset 0/8
    const int b_n = (lane & 7) + ((lane >> 4) << 3);   // B n within 16
    const int b_k = ((lane >> 3) & 1) << 3;            // B k-offset 0/8

#pragma unroll
    for (int k = 0; k < 128; k += 16) {
        uint32_t ah[2][4], al[2][4];
#pragma unroll
        for (int mt = 0; mt < 2; mt++) {
            const int r = (wm * 32 + mt * 16 + a_r) * PADH + k + a_c;
            ldmx4(ah[mt], sAh + r);
            ldmx4(al[mt], sAl + r);
        }
        uint32_t bh[8][2], bl[8][2];
#pragma unroll
        for (int p = 0; p < 4; p++) {
            const int off = (wn * 64 + p * 16 + b_n) * PADH + k + b_k;
            uint32_t t[4];
            ldmx4(t, sBh + off);
            bh[2 * p][0] = t[0]; bh[2 * p][1] = t[1];
            bh[2 * p + 1][0] = t[2]; bh[2 * p + 1][1] = t[3];
            ldmx4(t, sBl + off);
            bl[2 * p][0] = t[0]; bl[2 * p][1] = t[1];
            bl[2 * p + 1][0] = t[2]; bl[2 * p + 1][1] = t[3];
        }
#pragma unroll
        for (int mt = 0; mt < 2; mt++)
#pragma unroll
            for (int nt = 0; nt < 8; nt++) {
                mma16816(acc[mt][nt], ah[mt], bh[nt]);
                mma16816(acc[mt][nt], ah[mt], bl[nt]);
                mma16816(acc[mt][nt], al[mt], bh[nt]);
            }
    }

    // ---- epilogue: each (c0,c1)/(c2,c3) is one half2 column pair ----
    const int r_in = lane >> 2;             // 0..7
    const int cp = lane & 3;                // col-pair within n-tile
#pragma unroll
    for (int mt = 0; mt < 2; mt++) {
        int gr0 = row0 + wm * 32 + mt * 16 + r_in;
        int gr1 = gr0 + 8;
        float d0 = (gr0 < M) ? g_dinv[gr0] : 0.f;
        float d1 = (gr1 < M) ? g_dinv[gr1] : 0.f;
#pragma unroll
        for (int nt = 0; nt < 8; nt++) {
            int cpi = wn * 32 + nt * 4 + cp;
            if (gr0 < M)
                g_h16[(size_t)gr0 * 64 + cpi] =
                    __floats2half2_rn(acc[mt][nt][0] * d0, acc[mt][nt][1] * d0);
            if (gr1 < M)
                g_h16[(size_t)gr1 * 64 + cpi] =
                    __floats2half2_rn(acc[mt][nt][2] * d1, acc[mt][nt][3] * d1);
        }
    }
}

// ---------------- fused aggregate + bias + LayerNorm + ReLU (warp per node) ----------------
__global__ void agg_ln_relu_kernel(const float* __restrict__ cb,
                                   const float* __restrict__ lg,
                                   const float* __restrict__ lb, int N) {
    int n = (blockIdx.x * blockDim.x + threadIdx.x) >> 5;
    int lane = threadIdx.x & 31;
    if (n >= N) return;
    const int* __restrict__ cs = g_csrc;
    const ull* __restrict__ hrow = (const ull*)g_h16 + lane;

    float a0, a1, a2, a3;
    {
        ull v = hrow[(size_t)n * 32];
        float2 f0 = __half22float2(*(__half2*)&v);
        float2 f1 = __half22float2(*((__half2*)&v + 1));
        a0 = f0.x; a1 = f0.y; a2 = f1.x; a3 = f1.y;
    }
    int e = g_start[n];
    int e1 = e + g_deg[n];
    for (; e + 4 <= e1; e += 4) {
        int s0 = cs[e], s1 = cs[e + 1], s2 = cs[e + 2], s3 = cs[e + 3];
        ull v0 = hrow[(size_t)s0 * 32];
        ull v1 = hrow[(size_t)s1 * 32];
        ull v2 = hrow[(size_t)s2 * 32];
        ull v3 = hrow[(size_t)s3 * 32];
#define ACC(v)                                                   \
        {                                                        \
            float2 f0 = __half22float2(*(__half2*)&(v));         \
            float2 f1 = __half22float2(*((__half2*)&(v) + 1));   \
            a0 += f0.x; a1 += f0.y; a2 += f1.x; a3 += f1.y;      \
        }
        ACC(v0) ACC(v1) ACC(v2) ACC(v3)
    }
    for (; e < e1; e++) {
        ull v = hrow[(size_t)cs[e] * 32];
        ACC(v)
    }
#undef ACC
    float di = g_dinv[n];
    int c = lane * 4;
    a0 = fmaf(di, a0, cb[c]);
    a1 = fmaf(di, a1, cb[c + 1]);
    a2 = fmaf(di, a2, cb[c + 2]);
    a3 = fmaf(di, a3, cb[c + 3]);
    float s = a0 + a1 + a2 + a3;
#pragma unroll
    for (int o = 16; o > 0; o >>= 1) s += __shfl_xor_sync(0xffffffffu, s, o);
    float mu = s * (1.0f / 128.0f);
    float d0 = a0 - mu, d1 = a1 - mu, d2 = a2 - mu, d3 = a3 - mu;
    float v = d0 * d0 + d1 * d1 + d2 * d2 + d3 * d3;
#pragma unroll
    for (int o = 16; o > 0; o >>= 1) v += __shfl_xor_sync(0xffffffffu, v, o);
    float inv = rsqrtf(v * (1.0f / 128.0f) + LNEPS);
    float4 o4;
    o4.x = fmaxf(0.f, fmaf(d0 * inv, lg[c + 0], lb[c + 0]));
    o4.y = fmaxf(0.f, fmaf(d1 * inv, lg[c + 1], lb[c + 1]));
    o4.z = fmaxf(0.f, fmaf(d2 * inv, lg[c + 2], lb[c + 2]));
    o4.w = fmaxf(0.f, fmaf(d3 * inv, lg[c + 3], lb[c + 3]));
    ((float4*)g_act)[(size_t)n * 32 + lane] = o4;
}

// ---------------- output GEMM: out[M,40] = X[M,128] @ W[128,40] + b (f32x2) ----------------
__global__ __launch_bounds__(128)
void out_gemm_kernel(const float* __restrict__ X, const float* __restrict__ Wp,
                     const float* __restrict__ bp, float* __restrict__ out, int M) {
    __shared__ float ws[128 * 40];
    __shared__ float xs[128][33];
    int tid = threadIdx.x;
    int n0 = blockIdx.x << 7;
    for (int i = tid; i < 128 * 40; i += 128) ws[i] = Wp[i];
    ull acc[20];
#pragma unroll
    for (int j = 0; j < 20; j++) acc[j] = 0ull;
    for (int kt = 0; kt < 4; kt++) {
        __syncthreads();
#pragma unroll
        for (int i = 0; i < 8; i++) {
            int f = tid + i * 128;
            int r = f >> 3;
            int c = (f & 7) << 2;
            float4 v = make_float4(0.f, 0.f, 0.f, 0.f);
            int gr = n0 + r;
            if (gr < M) v = *(const float4*)(X + (size_t)gr * 128 + kt * 32 + c);
            xs[r][c] = v.x; xs[r][c + 1] = v.y; xs[r][c + 2] = v.z; xs[r][c + 3] = v.w;
        }
        __syncthreads();
#pragma unroll
        for (int k = 0; k < 32; k++) {
            ull xv = dup2(xs[tid][k]);
            const ull* w2 = (const ull*)(ws + (size_t)(kt * 32 + k) * 40);
#pragma unroll
            for (int j = 0; j < 20; j++) fma2(acc[j], xv, w2[j]);
        }
    }
    int n = n0 + tid;
    if (n < M) {
        const ull* b2 = (const ull*)bp;
#pragma unroll
        for (int j = 0; j < 20; j++)
            *(ull*)(out + (size_t)n * 40 + 2 * j) = add2(acc[j], b2[j]);
    }
}

// ---------------- launch ----------------
extern "C" void kernel_launch(void* const* d_in, const int* in_sizes, int n_in,
                              void* d_out, int out_size) {
    const float* x      = (const float*)d_in[0];
    const void*  ei     = d_in[1];
    const float* conv_w = (const float*)d_in[2];
    const float* conv_b = (const float*)d_in[3];
    const float* ln_g   = (const float*)d_in[4];
    const float* ln_b   = (const float*)d_in[5];
    const float* wout   = (const float*)d_in[6];
    const float* bout   = (const float*)d_in[7];
    float* out = (float*)d_out;

    const int N = NN;
    const int E = in_sizes[1] / 2;
    const int SMEMSZ = 4 * 128 * PADH * 2;   // 139264 B

    float* abuf;
    cudaGetSymbolAddress((void**)&abuf, g_act);
    cudaFuncSetAttribute(gemm_hmma, cudaFuncAttributeMaxDynamicSharedMemorySize, SMEMSZ);

    detect_zero_kernel<<<1, 1024>>>(ei, N);
    convert_count<<<(E + 255) / 256, 256>>>(ei, E);
    alloc_kernel<<<(N + 1023) / 1024, 1024>>>(N);
    fill_kernel<<<(E + 255) / 256, 256>>>(ei, E);
    wprep_kernel<<<(3 * 16384 + 255) / 256, 256>>>(conv_w);

    const float* cur = x;
    for (int l = 0; l < 3; l++) {
        gemm_hmma<<<(N + 127) / 128, 256, SMEMSZ>>>(cur, l, N);
        agg_ln_relu_kernel<<<(N + 7) / 8, 256>>>(conv_b + (size_t)l * 128,
                                                 ln_g + (size_t)l * 128,
                                                 ln_b + (size_t)l * 128, N);
        cur = abuf;
    }
    out_gemm_kernel<<<(N + 127) / 128, 128>>>(abuf, wout, bout, out, N);
}